// round 1
// baseline (speedup 1.0000x reference)
#include <cuda_runtime.h>
#include <cstdint>
#include <cstddef>

// Problem constants (fixed by the dataset)
#define B_DIM   256
#define D_DIM   512
#define T_STEPS 256

#define TPB             256
#define CTAS_PER_GROUP  16
#define NGROUPS         8
#define NCTAS           (NGROUPS * CTAS_PER_GROUP)   // 128 <= 148 SMs -> all resident
#define BM              32
#define BN              32

// Per-(group, step) arrival counters. Zero-initialized at module load.
// Monotonic barrier: never reset, target derived from atomicAdd return value,
// so correctness run + graph capture + N replays all work.
__device__ unsigned int g_flags[NGROUPS][T_STEPS];

__global__ void __launch_bounds__(TPB, 1)
koopman_scan_kernel(const float* __restrict__ z0,
                    const float* __restrict__ Kmat,
                    float* __restrict__ out)
{
    const int cta = blockIdx.x;
    const int g   = cta >> 4;       // row group 0..7   (rows m0..m0+31)
    const int ct  = cta & 15;       // col tile  0..15  (cols c0..c0+31)
    const int m0  = g * BM;
    const int c0  = ct * BN;
    const int tid = threadIdx.x;

    // K column slab, resident in smem for the whole kernel: Ks[k][c] = K[k][c0+c]
    extern __shared__ float Ks[];   // [D_DIM][BN] = 64 KB
    for (int idx = tid; idx < D_DIM * BN; idx += TPB) {
        const int kk = idx >> 5;
        const int cc = idx & 31;
        Ks[idx] = Kmat[kk * D_DIM + (c0 + cc)];
    }
    __syncthreads();

    // thread -> (1 output row, 4 output cols)
    const int row = m0 + (tid >> 3);        // 32 rows, 8 threads per row
    const int cl  = (tid & 7) << 2;         // local col, *4

    const unsigned int ks_base =
        (unsigned int)__cvta_generic_to_shared(Ks + cl);

    const float* z0row  = z0 + row * D_DIM;
    float*       outrow = out + (size_t)row * (T_STEPS * D_DIM);

    for (int t = 0; t < T_STEPS; ++t) {
        // step t reads z from slice t-1 (or z0), writes slice t
        const float* zrow = (t == 0) ? z0row : (outrow + (t - 1) * D_DIM);

        unsigned long long acc0 = 0ULL, acc1 = 0ULL;   // (c0..c1), (c2..c3) packed f32x2

        #pragma unroll 4
        for (int k = 0; k < D_DIM; k += 4) {
            // z row read: L2-cached, L1-bypassed (L1 is not coherent across SMs)
            const float4 zv = __ldcg(reinterpret_cast<const float4*>(zrow + k));
            const unsigned int ka = ks_base + (unsigned int)k * (BN * 4);
            unsigned long long zz, b0, b1;

            // k+0
            asm("ld.shared.v2.u64 {%0,%1},[%2];" : "=l"(b0), "=l"(b1) : "r"(ka));
            asm("mov.b64 %0,{%1,%1};"            : "=l"(zz) : "f"(zv.x));
            asm("fma.rn.f32x2 %0,%1,%2,%0;"      : "+l"(acc0) : "l"(zz), "l"(b0));
            asm("fma.rn.f32x2 %0,%1,%2,%0;"      : "+l"(acc1) : "l"(zz), "l"(b1));
            // k+1
            asm("ld.shared.v2.u64 {%0,%1},[%2];" : "=l"(b0), "=l"(b1) : "r"(ka + 1u * BN * 4));
            asm("mov.b64 %0,{%1,%1};"            : "=l"(zz) : "f"(zv.y));
            asm("fma.rn.f32x2 %0,%1,%2,%0;"      : "+l"(acc0) : "l"(zz), "l"(b0));
            asm("fma.rn.f32x2 %0,%1,%2,%0;"      : "+l"(acc1) : "l"(zz), "l"(b1));
            // k+2
            asm("ld.shared.v2.u64 {%0,%1},[%2];" : "=l"(b0), "=l"(b1) : "r"(ka + 2u * BN * 4));
            asm("mov.b64 %0,{%1,%1};"            : "=l"(zz) : "f"(zv.z));
            asm("fma.rn.f32x2 %0,%1,%2,%0;"      : "+l"(acc0) : "l"(zz), "l"(b0));
            asm("fma.rn.f32x2 %0,%1,%2,%0;"      : "+l"(acc1) : "l"(zz), "l"(b1));
            // k+3
            asm("ld.shared.v2.u64 {%0,%1},[%2];" : "=l"(b0), "=l"(b1) : "r"(ka + 3u * BN * 4));
            asm("mov.b64 %0,{%1,%1};"            : "=l"(zz) : "f"(zv.w));
            asm("fma.rn.f32x2 %0,%1,%2,%0;"      : "+l"(acc0) : "l"(zz), "l"(b0));
            asm("fma.rn.f32x2 %0,%1,%2,%0;"      : "+l"(acc1) : "l"(zz), "l"(b1));
        }

        // Unpack and store this thread's 4 outputs (coalesced 128B per row-group of 8 threads)
        float o0, o1, o2, o3;
        asm("mov.b64 {%0,%1},%2;" : "=f"(o0), "=f"(o1) : "l"(acc0));
        asm("mov.b64 {%0,%1},%2;" : "=f"(o2), "=f"(o3) : "l"(acc1));
        *reinterpret_cast<float4*>(outrow + t * D_DIM + c0 + cl) =
            make_float4(o0, o1, o2, o3);

        // Row-group barrier between steps (the 16 CTAs of this group are the
        // only producers AND the only consumers of these 32 z rows).
        if (t != T_STEPS - 1) {
            __syncthreads();
            if (tid == 0) {
                __threadfence();  // make this CTA's slice-t stores gpu-visible
                unsigned int old = atomicAdd(&g_flags[g][t], 1u);
                // this run's arrivals are in [16r, 16r+16); wait for 16(r+1)
                const unsigned int target = (old & ~15u) + 16u;
                unsigned int cur;
                do {
                    asm volatile("ld.acquire.gpu.u32 %0,[%1];"
                                 : "=r"(cur) : "l"(&g_flags[g][t]) : "memory");
                } while (cur < target);
            }
            __syncthreads();
        }
    }
}

extern "C" void kernel_launch(void* const* d_in, const int* in_sizes, int n_in,
                              void* d_out, int out_size)
{
    const float* z0 = (const float*)d_in[0];   // [256, 512] f32
    const float* K  = (const float*)d_in[1];   // [512, 512] f32
    // d_in[2] is T (=256), fixed by the problem; hardcoded.
    float* out = (float*)d_out;                // [256, 256, 512] f32

    cudaFuncSetAttribute(koopman_scan_kernel,
                         cudaFuncAttributeMaxDynamicSharedMemorySize,
                         D_DIM * BN * (int)sizeof(float));   // 64 KB

    koopman_scan_kernel<<<NCTAS, TPB, D_DIM * BN * sizeof(float)>>>(z0, K, out);
}

// round 3
// speedup vs baseline: 1.6696x; 1.6696x over previous
#include <cuda_runtime.h>
#include <cstdint>
#include <cstddef>

// Problem constants
#define DD      512
#define TSTEPS  256
#define BDIM    256

// GEMM tile config
#define TM  128
#define TN  64
#define KC  8
#define NCH (DD / KC)   // 64 k-chunks

// Scratch for K powers K^2, K^4, ..., K^128 (7 matrices, 7 MB, static: no allocs)
__device__ float g_pow[7][DD * DD];

#define FMA2(acc, a, b) \
    asm("fma.rn.f32x2 %0,%1,%2,%0;" : "+l"(acc) : "l"(a), "l"(b))

// C = A @ B with two row regions (M1 always a multiple of TM):
//   rows [0, M1):      addr = base1 + (r>>s)*hi + (r&mask)*DD   (interleaved out slices)
//   rows [M1, M1+M2):  addr = base2 + (r-M1)*DD                 (contiguous power matrix)
__global__ void __launch_bounds__(256)
gemm_step(const float* __restrict__ A1, float* __restrict__ C1,
          const float* __restrict__ A2, float* __restrict__ C2,
          const float* __restrict__ B,
          int M1, int s, int mask, int hiA, int hiC)
{
    __shared__ __align__(16) float              As[2][KC][TM]; // 8 KB, As[k][row]
    __shared__ __align__(16) unsigned long long Bs[2][KC][TN]; // 8 KB, duplicated f32x2

    const int tid    = threadIdx.x;
    const int rowBlk = blockIdx.x * TM;
    const int colBlk = blockIdx.y * TN;
    const int ty     = tid >> 4;      // 0..15 -> 8 rows each
    const int tx     = tid & 15;      // 0..15 -> 4 cols each

    // ---- A loader: 2 threads per row, one float4 of k per thread per chunk
    const int lrl  = tid >> 1;                 // local row 0..127
    const int lrow = rowBlk + lrl;
    const float* aptr;
    if (lrow < M1) aptr = A1 + (size_t)(lrow >> s) * hiA + (size_t)(lrow & mask) * DD;
    else           aptr = A2 + (size_t)(lrow - M1) * DD;
    aptr += (tid & 1) * 4;
    const int k0s = (tid & 1) * 4;

    // ---- B loader: threads 0..127 load one float4 each (8 k-rows x 64 cols)
    const bool   bload = (tid < 128);
    const int    bkr   = tid >> 4;            // k row in chunk 0..7
    const int    bcl   = (tid & 15) * 4;      // local col
    const float* bptr  = B + (size_t)bkr * DD + colBlk + bcl;

    float4 apre = *reinterpret_cast<const float4*>(aptr);
    float4 bpre = bload ? *reinterpret_cast<const float4*>(bptr)
                        : make_float4(0.f, 0.f, 0.f, 0.f);

    // stage chunk 0
    As[0][k0s + 0][lrl] = apre.x;
    As[0][k0s + 1][lrl] = apre.y;
    As[0][k0s + 2][lrl] = apre.z;
    As[0][k0s + 3][lrl] = apre.w;
    if (bload) {
        unsigned long long d0, d1, d2, d3;
        asm("mov.b64 %0,{%1,%1};" : "=l"(d0) : "f"(bpre.x));
        asm("mov.b64 %0,{%1,%1};" : "=l"(d1) : "f"(bpre.y));
        asm("mov.b64 %0,{%1,%1};" : "=l"(d2) : "f"(bpre.z));
        asm("mov.b64 %0,{%1,%1};" : "=l"(d3) : "f"(bpre.w));
        *reinterpret_cast<ulonglong2*>(&Bs[0][bkr][bcl])     = make_ulonglong2(d0, d1);
        *reinterpret_cast<ulonglong2*>(&Bs[0][bkr][bcl + 2]) = make_ulonglong2(d2, d3);
    }
    __syncthreads();

    unsigned long long acc[4][4];
    #pragma unroll
    for (int i = 0; i < 4; ++i)
        #pragma unroll
        for (int j = 0; j < 4; ++j) acc[i][j] = 0ULL;

    for (int ch = 0; ch < NCH; ++ch) {
        if (ch + 1 < NCH) {   // prefetch next chunk into registers
            apre = *reinterpret_cast<const float4*>(aptr + (ch + 1) * KC);
            if (bload)
                bpre = *reinterpret_cast<const float4*>(bptr + (size_t)(ch + 1) * KC * DD);
        }
        const int buf = ch & 1;

        #pragma unroll
        for (int k = 0; k < KC; ++k) {
            // A rows: pairs (0,1)(2,3)(4,5)(6,7) of this thread's 8 rows
            const ulonglong2 a01 =
                *reinterpret_cast<const ulonglong2*>(&As[buf][k][ty * 8]);
            const ulonglong2 a23 =
                *reinterpret_cast<const ulonglong2*>(&As[buf][k][ty * 8 + 4]);
            // B cols: pre-duplicated f32x2 values
            const ulonglong2 b01 =
                *reinterpret_cast<const ulonglong2*>(&Bs[buf][k][tx * 4]);
            const ulonglong2 b23 =
                *reinterpret_cast<const ulonglong2*>(&Bs[buf][k][tx * 4 + 2]);

            FMA2(acc[0][0], a01.x, b01.x); FMA2(acc[0][1], a01.x, b01.y);
            FMA2(acc[0][2], a01.x, b23.x); FMA2(acc[0][3], a01.x, b23.y);
            FMA2(acc[1][0], a01.y, b01.x); FMA2(acc[1][1], a01.y, b01.y);
            FMA2(acc[1][2], a01.y, b23.x); FMA2(acc[1][3], a01.y, b23.y);
            FMA2(acc[2][0], a23.x, b01.x); FMA2(acc[2][1], a23.x, b01.y);
            FMA2(acc[2][2], a23.x, b23.x); FMA2(acc[2][3], a23.x, b23.y);
            FMA2(acc[3][0], a23.y, b01.x); FMA2(acc[3][1], a23.y, b01.y);
            FMA2(acc[3][2], a23.y, b23.x); FMA2(acc[3][3], a23.y, b23.y);
        }

        if (ch + 1 < NCH) {   // stage next chunk into the other buffer
            const int nxt = (ch + 1) & 1;
            As[nxt][k0s + 0][lrl] = apre.x;
            As[nxt][k0s + 1][lrl] = apre.y;
            As[nxt][k0s + 2][lrl] = apre.z;
            As[nxt][k0s + 3][lrl] = apre.w;
            if (bload) {
                unsigned long long d0, d1, d2, d3;
                asm("mov.b64 %0,{%1,%1};" : "=l"(d0) : "f"(bpre.x));
                asm("mov.b64 %0,{%1,%1};" : "=l"(d1) : "f"(bpre.y));
                asm("mov.b64 %0,{%1,%1};" : "=l"(d2) : "f"(bpre.z));
                asm("mov.b64 %0,{%1,%1};" : "=l"(d3) : "f"(bpre.w));
                *reinterpret_cast<ulonglong2*>(&Bs[nxt][bkr][bcl])     = make_ulonglong2(d0, d1);
                *reinterpret_cast<ulonglong2*>(&Bs[nxt][bkr][bcl + 2]) = make_ulonglong2(d2, d3);
            }
            __syncthreads();
        }
    }

    // epilogue: unpack f32x2 accumulators, store 8 rows x 4 cols per thread
    float vout[8][4];
    #pragma unroll
    for (int rp = 0; rp < 4; ++rp)
        #pragma unroll
        for (int c = 0; c < 4; ++c) {
            float lo, hi;
            asm("mov.b64 {%0,%1},%2;" : "=f"(lo), "=f"(hi) : "l"(acc[rp][c]));
            vout[2 * rp][c]     = lo;
            vout[2 * rp + 1][c] = hi;
        }

    #pragma unroll
    for (int r = 0; r < 8; ++r) {
        const int crow = rowBlk + ty * 8 + r;
        float* cp;
        if (crow < M1) cp = C1 + (size_t)(crow >> s) * hiC + (size_t)(crow & mask) * DD;
        else           cp = C2 + (size_t)(crow - M1) * DD;
        *reinterpret_cast<float4*>(cp + colBlk + tx * 4) =
            make_float4(vout[r][0], vout[r][1], vout[r][2], vout[r][3]);
    }
}

extern "C" void kernel_launch(void* const* d_in, const int* in_sizes, int n_in,
                              void* d_out, int out_size)
{
    const float* z0 = (const float*)d_in[0];   // [256, 512]
    const float* K  = (const float*)d_in[1];   // [512, 512]
    float* out = (float*)d_out;                // [256, 256, 512]  out[b][t][d]

    float* P = nullptr;
    cudaGetSymbolAddress((void**)&P, g_pow);   // address query only, capture-safe

    // G0: slice 0 = z0 @ K   (A contiguous rows, C strided by T*D)
    gemm_step<<<dim3(BDIM / TM, DD / TN), 256>>>(
        z0, out, z0, out, K, BDIM, 0, 0, DD, TSTEPS * DD);

    // Doubling level j: [slices 0..n-1] @ K^n -> slices n..2n-1  (n = 2^j)
    // plus (j<7) appended rows: K^n @ K^n -> K^(2n) into g_pow[j]
    for (int j = 0; j < 8; ++j) {
        const int n  = 1 << j;
        const int M1 = BDIM * n;
        const int M2 = (j < 7) ? DD : 0;
        const float* Bop = (j == 0) ? K : (P + (size_t)(j - 1) * DD * DD);
        float*       Cp  = P + (size_t)j * DD * DD;   // unused when j==7 (M2=0)
        gemm_step<<<dim3((M1 + M2) / TM, DD / TN), 256>>>(
            out, out + (size_t)n * DD, Bop, Cp, Bop,
            M1, j, n - 1, TSTEPS * DD, TSTEPS * DD);
    }
}

// round 6
// speedup vs baseline: 6.6541x; 3.9854x over previous
#include <cuda_runtime.h>
#include <cuda_bf16.h>
#include <cstdint>
#include <cstddef>

#define DD      512
#define TSTEPS  256
#define BDIM    256
#define ZROWS   32768          // slices 0..127 kept as bf16 A-source

typedef unsigned short ushort_t;

// ---------------- static device storage (no allocs) ----------------
__device__ ushort_t g_zh[ZROWS * DD];        // z slices bf16 hi, [t][b][d]
__device__ ushort_t g_zl[ZROWS * DD];        // z slices bf16 lo
__device__ ushort_t g_z0h[BDIM * DD], g_z0l[BDIM * DD];
__device__ ushort_t g_pwh[8][DD * DD], g_pwl[8][DD * DD];    // K^(2^j) bf16
__device__ ushort_t g_pwth[8][DD * DD], g_pwtl[8][DD * DD];  // transposed [n][k]

// ---------------- helpers ----------------
__device__ __forceinline__ uint32_t smem_u32(const void* p) {
    uint32_t a;
    asm("{ .reg .u64 t; cvta.to.shared.u64 t, %1; cvt.u32.u64 %0, t; }"
        : "=r"(a) : "l"(p));
    return a;
}

#define CP16(dst, src) \
    asm volatile("cp.async.cg.shared.global [%0], [%1], 16;" \
                 :: "r"(dst), "l"(src) : "memory")
#define CP_COMMIT() asm volatile("cp.async.commit_group;" ::: "memory")
#define CP_WAIT0()  asm volatile("cp.async.wait_group 0;" ::: "memory")
#define CP_WAIT1()  asm volatile("cp.async.wait_group 1;" ::: "memory")

#define LDSM4(R, a) \
    asm volatile("ldmatrix.sync.aligned.m8n8.x4.shared.b16 {%0,%1,%2,%3},[%4];" \
                 : "=r"((R)[0]), "=r"((R)[1]), "=r"((R)[2]), "=r"((R)[3]) : "r"(a))

#define MMA(C, A, b0v, b1v) \
    asm volatile("mma.sync.aligned.m16n8k16.row.col.f32.bf16.bf16.f32 " \
                 "{%0,%1,%2,%3},{%4,%5,%6,%7},{%8,%9},{%0,%1,%2,%3};" \
                 : "+f"((C)[0]), "+f"((C)[1]), "+f"((C)[2]), "+f"((C)[3]) \
                 : "r"((A)[0]), "r"((A)[1]), "r"((A)[2]), "r"((A)[3]), \
                   "r"(b0v), "r"(b1v))

__device__ __forceinline__ void split_bf16(float f, ushort_t& h, ushort_t& l) {
    __nv_bfloat16 bh = __float2bfloat16_rn(f);
    float fl = f - __bfloat162float(bh);
    __nv_bfloat16 bl = __float2bfloat16_rn(fl);
    h = *reinterpret_cast<ushort_t*>(&bh);
    l = *reinterpret_cast<ushort_t*>(&bl);
}

// ---------------- prep: K -> pw0 / pwT0 bf16 ; z0 -> z0 bf16 ----------------
__global__ void prep_kernel(const float* __restrict__ K, const float* __restrict__ z0)
{
    const int r = blockIdx.x;
    if (r < DD) {
        for (int c = threadIdx.x; c < DD; c += blockDim.x) {
            ushort_t h, l; split_bf16(K[r * DD + c], h, l);
            g_pwh[0][r * DD + c] = h;  g_pwl[0][r * DD + c] = l;
            g_pwth[0][c * DD + r] = h; g_pwtl[0][c * DD + r] = l;
        }
    } else {
        const int rr = r - DD;
        for (int c = threadIdx.x; c < DD; c += blockDim.x) {
            ushort_t h, l; split_bf16(z0[rr * DD + c], h, l);
            g_z0h[rr * DD + c] = h;  g_z0l[rr * DD + c] = l;
        }
    }
}

__global__ void transp_kernel(int j)
{
    const int k = blockIdx.x;
    const ushort_t* sh = g_pwh[j];  const ushort_t* sl = g_pwl[j];
    ushort_t* dh = g_pwth[j];       ushort_t* dl = g_pwtl[j];
    for (int c = threadIdx.x; c < DD; c += blockDim.x) {
        dh[c * DD + k] = sh[k * DD + c];
        dl[c * DD + k] = sl[k * DD + c];
    }
}

// ---------------- warp-MMA GEMM: D = A @ B^T, 3-term bf16 split -------------
#define KC     64
#define CHUNKS 8
#define PLANE  16384            // 128 rows x 64 bf16
#define STAGE  65536            // 4 planes: Ah, Al, Bh, Bl

// row [0,M1): A1 (z slices, contiguous rows), fp32 out + bf16 z copy
// row >= M1:  A2 (power matrix) -> nxt bf16 planes (next power)
#define LOAD_CHUNK(chv, sv) do {                                               \
    const int kbase_ = (chv) * KC;                                             \
    _Pragma("unroll")                                                          \
    for (int p_ = 0; p_ < 4; ++p_) {                                           \
        const ushort_t* sp_ = srcs[p_];                                        \
        _Pragma("unroll")                                                      \
        for (int rep_ = 0; rep_ < 4; ++rep_) {                                 \
            const int c_   = tid + rep_ * 256;                                 \
            const int row_ = c_ >> 3;                                          \
            const int cc_  = (c_ & 7) * 8;                                     \
            const ushort_t* src_ = sp_ + (size_t)row_ * DD + kbase_ + cc_;     \
            const uint32_t dst_ = sbu + (uint32_t)(sv) * STAGE                 \
                + (uint32_t)p_ * PLANE + (uint32_t)(row_ * 128)                \
                + (((uint32_t)(cc_ * 2)) ^ ((uint32_t)(row_ & 7) << 4));       \
            CP16(dst_, src_);                                                  \
        }                                                                      \
    }                                                                          \
} while (0)

__global__ void __launch_bounds__(256, 1)
gemm_tc(const ushort_t* __restrict__ a1h, const ushort_t* __restrict__ a1l,
        const ushort_t* __restrict__ a2h, const ushort_t* __restrict__ a2l,
        const ushort_t* __restrict__ bh,  const ushort_t* __restrict__ bl,
        float* __restrict__ outF,
        ushort_t* __restrict__ zH, ushort_t* __restrict__ zL,
        ushort_t* __restrict__ nxtH, ushort_t* __restrict__ nxtL,
        int M1, int tofs, int dstOfs)
{
    extern __shared__ char dsm[];
    char* sb = (char*)(((uintptr_t)dsm + 1023) & ~(uintptr_t)1023);
    const uint32_t sbu = smem_u32(sb);

    const int tid  = threadIdx.x;
    const int wid  = tid >> 5;
    const int lane = tid & 31;
    const int wm   = wid & 3;          // warp row  (32 rows)
    const int wn   = wid >> 2;         // warp col  (64 cols)
    const int rowBlk = blockIdx.x * 128;
    const int n0     = blockIdx.y * 128;

    // source row bases (CTA uniform: M1 % 128 == 0)
    const bool inA1 = (rowBlk < M1);
    const ushort_t* srcs[4];
    const size_t aOfs = (size_t)(inA1 ? rowBlk : (rowBlk - M1)) * DD;
    srcs[0] = (inA1 ? a1h : a2h) + aOfs;
    srcs[1] = (inA1 ? a1l : a2l) + aOfs;
    srcs[2] = bh + (size_t)n0 * DD;
    srcs[3] = bl + (size_t)n0 * DD;

    // ldmatrix per-lane address precompute (SW128: col ^ ((row&7)<<4))
    uint32_t aOff[2], aXor[2];
    {
        const int r0 = wm * 32 + (lane & 15);
        #pragma unroll
        for (int mt = 0; mt < 2; ++mt) {
            const int r = r0 + mt * 16;
            aOff[mt] = (uint32_t)(r * 128);
            aXor[mt] = (uint32_t)((r & 7) << 4);
        }
    }
    const uint32_t aColB = (uint32_t)((lane >> 4) * 16);
    uint32_t bOff[4], bXor[4];
    {
        const int r0 = wn * 64 + (lane & 7) + 8 * (lane >> 4);
        #pragma unroll
        for (int np = 0; np < 4; ++np) {
            const int r = r0 + np * 16;
            bOff[np] = (uint32_t)(r * 128);
            bXor[np] = (uint32_t)((r & 7) << 4);
        }
    }
    const uint32_t bColB = (uint32_t)(((lane >> 3) & 1) * 16);

    float acc[2][8][4];
    #pragma unroll
    for (int mt = 0; mt < 2; ++mt)
        #pragma unroll
        for (int nt = 0; nt < 8; ++nt)
            #pragma unroll
            for (int q = 0; q < 4; ++q) acc[mt][nt][q] = 0.f;

    LOAD_CHUNK(0, 0); CP_COMMIT();

    for (int ch = 0; ch < CHUNKS; ++ch) {
        if (ch + 1 < CHUNKS) { LOAD_CHUNK(ch + 1, (ch + 1) & 1); CP_COMMIT(); CP_WAIT1(); }
        else                 { CP_WAIT0(); }
        __syncthreads();

        const uint32_t base = sbu + (uint32_t)(ch & 1) * STAGE;
        #pragma unroll
        for (int k16 = 0; k16 < 4; ++k16) {
            const uint32_t cA = (uint32_t)(k16 * 32) + aColB;
            const uint32_t cB = (uint32_t)(k16 * 32) + bColB;
            uint32_t ah[2][4], al[2][4], bhf[4][4], blf[4][4];
            #pragma unroll
            for (int mt = 0; mt < 2; ++mt) {
                LDSM4(ah[mt], base + 0 * PLANE + aOff[mt] + (cA ^ aXor[mt]));
                LDSM4(al[mt], base + 1 * PLANE + aOff[mt] + (cA ^ aXor[mt]));
            }
            #pragma unroll
            for (int np = 0; np < 4; ++np) {
                LDSM4(bhf[np], base + 2 * PLANE + bOff[np] + (cB ^ bXor[np]));
                LDSM4(blf[np], base + 3 * PLANE + bOff[np] + (cB ^ bXor[np]));
            }
            #pragma unroll
            for (int mt = 0; mt < 2; ++mt)
                #pragma unroll
                for (int nt = 0; nt < 8; ++nt) {
                    const uint32_t* bp = &bhf[nt >> 1][(nt & 1) * 2];
                    const uint32_t* lp = &blf[nt >> 1][(nt & 1) * 2];
                    MMA(acc[mt][nt], ah[mt], bp[0], bp[1]);   // hi*hi
                    MMA(acc[mt][nt], ah[mt], lp[0], lp[1]);   // hi*lo
                    MMA(acc[mt][nt], al[mt], bp[0], bp[1]);   // lo*hi
                }
        }
        __syncthreads();
    }

    // epilogue: D row = lane>>2 (+8), col = 2*(lane&3)
    #pragma unroll
    for (int mt = 0; mt < 2; ++mt)
        #pragma unroll
        for (int nt = 0; nt < 8; ++nt) {
            const int rbase = rowBlk + wm * 32 + mt * 16 + (lane >> 2);
            const int col   = n0 + wn * 64 + nt * 8 + 2 * (lane & 3);
            #pragma unroll
            for (int half = 0; half < 2; ++half) {
                const int g = rbase + half * 8;
                const float c0 = acc[mt][nt][half * 2];
                const float c1 = acc[mt][nt][half * 2 + 1];
                ushort_t h0, l0, h1, l1;
                split_bf16(c0, h0, l0); split_bf16(c1, h1, l1);
                const uint32_t ph = (uint32_t)h0 | ((uint32_t)h1 << 16);
                const uint32_t pl = (uint32_t)l0 | ((uint32_t)l1 << 16);
                if (inA1) {
                    float2 v; v.x = c0; v.y = c1;
                    *reinterpret_cast<float2*>(
                        outF + ((size_t)(g & 255) * TSTEPS + (size_t)tofs + (g >> 8)) * DD
                             + col) = v;
                    const int zr = g + dstOfs;
                    if (zr < ZROWS) {
                        *reinterpret_cast<uint32_t*>(zH + (size_t)zr * DD + col) = ph;
                        *reinterpret_cast<uint32_t*>(zL + (size_t)zr * DD + col) = pl;
                    }
                } else {
                    const size_t o = (size_t)(g - M1) * DD + col;
                    *reinterpret_cast<uint32_t*>(nxtH + o) = ph;
                    *reinterpret_cast<uint32_t*>(nxtL + o) = pl;
                }
            }
        }
}

// ---------------- host ----------------
extern "C" void kernel_launch(void* const* d_in, const int* in_sizes, int n_in,
                              void* d_out, int out_size)
{
    const float* z0 = (const float*)d_in[0];
    const float* K  = (const float*)d_in[1];
    float* out = (float*)d_out;

    ushort_t *zh, *zl, *z0h, *z0l, *pwh, *pwl, *pwth, *pwtl;
    cudaGetSymbolAddress((void**)&zh,   g_zh);
    cudaGetSymbolAddress((void**)&zl,   g_zl);
    cudaGetSymbolAddress((void**)&z0h,  g_z0h);
    cudaGetSymbolAddress((void**)&z0l,  g_z0l);
    cudaGetSymbolAddress((void**)&pwh,  g_pwh);
    cudaGetSymbolAddress((void**)&pwl,  g_pwl);
    cudaGetSymbolAddress((void**)&pwth, g_pwth);
    cudaGetSymbolAddress((void**)&pwtl, g_pwtl);

    const int SMEM = 2 * STAGE + 1024;
    cudaFuncSetAttribute(gemm_tc, cudaFuncAttributeMaxDynamicSharedMemorySize, SMEM);

    prep_kernel<<<DD + BDIM, 256>>>(K, z0);

    // G0: slice 0 = z0 @ K
    gemm_tc<<<dim3(2, 4), 256, SMEM>>>(
        z0h, z0l, z0h, z0l, pwth, pwtl,
        out, zh, zl, pwh, pwl, /*M1=*/256, /*tofs=*/0, /*dstOfs=*/0);

    // Level j: [slices 0..n-1] @ K^n -> slices n..2n-1 ; append K^n @ K^n -> K^(2n)
    for (int j = 0; j < 8; ++j) {
        const int n  = 1 << j;
        const int M1 = BDIM * n;
        const int rows = M1 + ((j < 7) ? DD : 0);
        const size_t mo = (size_t)j * DD * DD;
        const size_t no = (size_t)(j < 7 ? j + 1 : 0) * DD * DD;
        gemm_tc<<<dim3(rows / 128, 4), 256, SMEM>>>(
            zh, zl, pwh + mo, pwl + mo, pwth + mo, pwtl + mo,
            out, zh, zl, pwh + no, pwl + no,
            M1, /*tofs=*/n, /*dstOfs=*/M1);
        if (j < 7) transp_kernel<<<DD, 256>>>(j + 1);
    }
}